// round 9
// baseline (speedup 1.0000x reference)
#include <cuda_runtime.h>
#include <cuda_bf16.h>
#include <math.h>
#include <stdint.h>

// Problem dims (fixed by reference)
#define Bb 2
#define Dd 256
#define Tt 8
#define HW 1024          // H*W = 32*32
#define NROWS 16384      // B*T*H*W
#define KCODES 8192

// ---------------- scratch (__device__ globals; no allocation allowed) ----------------
__device__ float g_zf[NROWS * Dd];          // z transposed to [N, D]
__device__ float g_zq[NROWS * Dd];          // gathered codes [N, D]
__device__ float g_Hb[KCODES * Dd];         // gelu(emb @ w1^T)
__device__ float g_Cb[KCODES * Dd];         // codebook [K, D]
__device__ float g_cn2[KCODES];             // ||c_k||^2
__device__ unsigned long long g_rowmin[NROWS];   // global top-1 (key||idx)
__device__ unsigned long long g_rowmin2[NROWS];  // global top-2 (key||idx)
__device__ int g_counts[KCODES];
__device__ float g_zsum[Dd];
__device__ float g_csum[Dd];
__device__ double g_z2sum;
__device__ double g_losssum;
// bf16 2-way splits for tensor-core distance GEMM
__device__ __nv_bfloat16 g_zh[NROWS * Dd];
__device__ __nv_bfloat16 g_zl[NROWS * Dd];
__device__ __nv_bfloat16 g_ch[KCODES * Dd];
__device__ __nv_bfloat16 g_cl[KCODES * Dd];

// ================= helpers =================
__device__ __forceinline__ uint32_t smem_u32(const void* p) {
    uint32_t a;
    asm("{ .reg .u64 t; cvta.to.shared.u64 t, %1; cvt.u32.u64 %0, t; }" : "=r"(a) : "l"(p));
    return a;
}
__device__ __forceinline__ unsigned int float_key(float f) {
    unsigned int b = __float_as_uint(f);
    return (b & 0x80000000u) ? ~b : (b | 0x80000000u);
}
__device__ __forceinline__ float key_to_float(unsigned int k) {
    return (k & 0x80000000u) ? __uint_as_float(k & 0x7FFFFFFFu)
                             : __uint_as_float(~k);
}

#define LDSM4(R0, R1, R2, R3, addr) \
    asm volatile("ldmatrix.sync.aligned.m8n8.x4.shared.b16 {%0,%1,%2,%3}, [%4];" \
        : "=r"(R0), "=r"(R1), "=r"(R2), "=r"(R3) : "r"(addr))

#define MMA16816(D, A, B0, B1) \
    asm volatile("mma.sync.aligned.m16n8k16.row.col.f32.bf16.bf16.f32 " \
        "{%0,%1,%2,%3}, {%4,%5,%6,%7}, {%8,%9}, {%0,%1,%2,%3};" \
        : "+f"((D)[0]), "+f"((D)[1]), "+f"((D)[2]), "+f"((D)[3]) \
        : "r"((A)[0]), "r"((A)[1]), "r"((A)[2]), "r"((A)[3]), "r"(B0), "r"(B1))

// ---------------- init ----------------
__global__ void init_kernel() {
    int i = blockIdx.x * 256 + threadIdx.x;
    if (i < NROWS) { g_rowmin[i] = ~0ULL; g_rowmin2[i] = ~0ULL; }
    if (i < KCODES) g_counts[i] = 0;
    if (i < Dd) { g_zsum[i] = 0.f; g_csum[i] = 0.f; }
    if (i == 0) { g_z2sum = 0.0; g_losssum = 0.0; }
}

// ---------------- transpose z [B,D,T,H,W] -> zf [N, D] ----------------
__global__ void transpose_in_kernel(const float* __restrict__ z) {
    __shared__ float tile[32][33];
    int bt = blockIdx.z;
    int b = bt / Tt, t = bt % Tt;
    int hw0 = blockIdx.x * 32, d0 = blockIdx.y * 32;
    const float* src = z + (size_t)b * Dd * Tt * HW + (size_t)t * HW;
    for (int r = threadIdx.y; r < 32; r += 8)
        tile[r][threadIdx.x] = src[(size_t)(d0 + r) * (Tt * HW) + hw0 + threadIdx.x];
    __syncthreads();
    float* dst = g_zf + (size_t)bt * HW * Dd;
    for (int r = threadIdx.y; r < 32; r += 8)
        dst[(size_t)(hw0 + r) * Dd + d0 + threadIdx.x] = tile[threadIdx.x][r];
}

// ---------------- transpose zq [N,D] -> out [B,D,T,H,W] ----------------
__global__ void transpose_out_kernel(float* __restrict__ out) {
    __shared__ float tile[32][33];
    int bt = blockIdx.z;
    int b = bt / Tt, t = bt % Tt;
    int hw0 = blockIdx.x * 32, d0 = blockIdx.y * 32;
    const float* src = g_zq + (size_t)bt * HW * Dd;
    for (int r = threadIdx.y; r < 32; r += 8)
        tile[r][threadIdx.x] = src[(size_t)(hw0 + r) * Dd + d0 + threadIdx.x];
    __syncthreads();
    float* dst = out + (size_t)b * Dd * Tt * HW + (size_t)t * HW;
    for (int r = threadIdx.y; r < 32; r += 8)
        dst[(size_t)(d0 + r) * (Tt * HW) + hw0 + threadIdx.x] = tile[threadIdx.x][r];
}

// ---------------- bf16 split kernels ----------------
__global__ void split_z_kernel() {
    int i = blockIdx.x * 256 + threadIdx.x;
    float x = g_zf[i];
    __nv_bfloat16 h = __float2bfloat16_rn(x);
    g_zh[i] = h;
    g_zl[i] = __float2bfloat16_rn(x - __bfloat162float(h));
}
__global__ void split_c_kernel() {
    int i = blockIdx.x * 256 + threadIdx.x;
    float x = g_Cb[i];
    __nv_bfloat16 h = __float2bfloat16_rn(x);
    g_ch[i] = h;
    g_cl[i] = __float2bfloat16_rn(x - __bfloat162float(h));
}

// ---------------- column sums ----------------
__global__ void colsum_z_kernel() {
    int tid = threadIdx.x;
    int row0 = blockIdx.x * 64;
    float s = 0.f, sq = 0.f;
    for (int r = 0; r < 64; r++) {
        float v = g_zf[(size_t)(row0 + r) * Dd + tid];
        s += v; sq += v * v;
    }
    atomicAdd(&g_zsum[tid], s);
    __shared__ float red[256];
    red[tid] = sq; __syncthreads();
    for (int o = 128; o; o >>= 1) { if (tid < o) red[tid] += red[tid + o]; __syncthreads(); }
    if (tid == 0) atomicAdd(&g_z2sum, (double)red[0]);
}
__global__ void colsum_c_kernel() {
    int tid = threadIdx.x;
    int row0 = blockIdx.x * 64;
    float s = 0.f;
    for (int r = 0; r < 64; r++) s += g_Cb[(size_t)(row0 + r) * Dd + tid];
    atomicAdd(&g_csum[tid], s);
}

// ---------------- per-row ||c||^2 ----------------
__global__ void rownorm_kernel() {
    int row = blockIdx.x * 8 + (threadIdx.x >> 5);
    int lane = threadIdx.x & 31;
    const float* p = g_Cb + (size_t)row * Dd;
    float s = 0.f;
    for (int i = lane; i < Dd; i += 32) { float v = p[i]; s += v * v; }
    for (int o = 16; o; o >>= 1) s += __shfl_down_sync(0xFFFFFFFFu, s, o);
    if (lane == 0) g_cn2[row] = s;
}

// ---------------- codebook SGEMM (fp32, exact; small) ----------------
#define BM 128
#define BN 128
#define BKk 16

template<int MODE>   // 0: store plain, 1: store gelu
__global__ __launch_bounds__(256) void gemm_nt_kernel(
    const float* __restrict__ A, const float* __restrict__ B, float* __restrict__ Cout)
{
    __shared__ __align__(16) float sA[BKk][BM];
    __shared__ __align__(16) float sB[BKk][BN];
    int tid = threadIdx.x;
    int tx = tid & 15, ty = tid >> 4;
    int m0 = blockIdx.y * BM;
    int n0 = blockIdx.x * BN;

    float acc[8][8];
#pragma unroll
    for (int i = 0; i < 8; i++)
#pragma unroll
        for (int j = 0; j < 8; j++) acc[i][j] = 0.f;

    const float* Ab = A + (size_t)m0 * Dd;
    const float* Bt = B + (size_t)n0 * Dd;

    for (int kt = 0; kt < Dd; kt += BKk) {
#pragma unroll
        for (int s = 0; s < 2; s++) {
            int v = tid + s * 256;
            int row = v >> 2;
            int kq = (v & 3) << 2;
            float4 fa = *(const float4*)(Ab + (size_t)row * Dd + kt + kq);
            sA[kq + 0][row] = fa.x; sA[kq + 1][row] = fa.y;
            sA[kq + 2][row] = fa.z; sA[kq + 3][row] = fa.w;
            float4 fb = *(const float4*)(Bt + (size_t)row * Dd + kt + kq);
            sB[kq + 0][row] = fb.x; sB[kq + 1][row] = fb.y;
            sB[kq + 2][row] = fb.z; sB[kq + 3][row] = fb.w;
        }
        __syncthreads();
#pragma unroll
        for (int kk = 0; kk < BKk; kk++) {
            float ra[8], rb[8];
#pragma unroll
            for (int i = 0; i < 8; i++) ra[i] = sA[kk][ty * 8 + i];
#pragma unroll
            for (int j = 0; j < 8; j++) rb[j] = sB[kk][tx * 8 + j];
#pragma unroll
            for (int i = 0; i < 8; i++)
#pragma unroll
                for (int j = 0; j < 8; j++) acc[i][j] += ra[i] * rb[j];
        }
        __syncthreads();
    }

#pragma unroll
    for (int i = 0; i < 8; i++)
#pragma unroll
        for (int j = 0; j < 8; j++) {
            float v = acc[i][j];
            if (MODE == 1) v = 0.5f * v * (1.0f + erff(v * 0.70710678118654752f));
            Cout[(size_t)(m0 + ty * 8 + i) * Dd + n0 + tx * 8 + j] = v;
        }
}

// ================= HMMA (mma.sync bf16x3) distance GEMM + fused top-2 argmin =================
// CTA tile: 128 z-rows x 128 codes. 8 warps (2 along M x 4 along N), warp tile 64x32.
// K in chunks of 32 bf16. Products: Ah*Bh + Ah*Bl + Al*Bh (lo*lo dropped).
// Smem rows padded to 80B for conflict-free ldmatrix.
#define RSB 80                      // row stride bytes (64 data + 16 pad)
#define TILE_B (128 * RSB)          // 10240 bytes per operand tile
#define OFF_AH 0
#define OFF_AL (TILE_B)
#define OFF_BH (2 * TILE_B)
#define OFF_BL (3 * TILE_B)

__global__ __launch_bounds__(256, 2) void vq_dist_hmma_kernel() {
    __shared__ __align__(16) unsigned char sm[4 * TILE_B];
    __shared__ float s_cn2[128];
    const int tid = threadIdx.x;
    const int lane = tid & 31, wid = tid >> 5;
    const int n0 = blockIdx.x * 128;
    const int m0 = blockIdx.y * 128;
    const int wm = (wid & 1) * 64;
    const int wn = (wid >> 1) * 32;

    if (tid < 128) s_cn2[tid] = g_cn2[n0 + tid];

    float acc[4][4][4];
#pragma unroll
    for (int a = 0; a < 4; a++)
#pragma unroll
        for (int b = 0; b < 4; b++)
#pragma unroll
            for (int c = 0; c < 4; c++) acc[a][b][c] = 0.f;

    const uint32_t sbase = smem_u32(sm);
    const uint32_t aOff = (uint32_t)(wm + (lane & 15)) * RSB + 16u * (lane >> 4);
    const uint32_t bOff = (uint32_t)(wn + (lane & 7) + 8 * (lane >> 4)) * RSB +
                          16u * ((lane >> 3) & 1);

    for (int ch = 0; ch < 8; ch++) {
        const int k0 = ch * 32;
        if (ch) __syncthreads();
#pragma unroll
        for (int s = 0; s < 2; s++) {
            int idx = tid + s * 256;
            int r = idx >> 2, cc = idx & 3;
            uint32_t d = (uint32_t)r * RSB + (uint32_t)cc * 16;
            size_t ga = (size_t)(m0 + r) * Dd + k0 + cc * 8;
            size_t gb = (size_t)(n0 + r) * Dd + k0 + cc * 8;
            *(uint4*)(sm + OFF_AH + d) = *(const uint4*)(g_zh + ga);
            *(uint4*)(sm + OFF_AL + d) = *(const uint4*)(g_zl + ga);
            *(uint4*)(sm + OFF_BH + d) = *(const uint4*)(g_ch + gb);
            *(uint4*)(sm + OFF_BL + d) = *(const uint4*)(g_cl + gb);
        }
        __syncthreads();
#pragma unroll
        for (int kk = 0; kk < 2; kk++) {
            const uint32_t koff = kk * 32;
            uint32_t bh[8], bl[8];
#pragma unroll
            for (int p = 0; p < 2; p++) {
                uint32_t ba = sbase + bOff + (uint32_t)p * (16 * RSB) + koff;
                LDSM4(bh[p * 4 + 0], bh[p * 4 + 1], bh[p * 4 + 2], bh[p * 4 + 3],
                      ba + OFF_BH);
                LDSM4(bl[p * 4 + 0], bl[p * 4 + 1], bl[p * 4 + 2], bl[p * 4 + 3],
                      ba + OFF_BL);
            }
#pragma unroll
            for (int mi = 0; mi < 4; mi++) {
                uint32_t ah[4], al[4];
                uint32_t aa = sbase + aOff + (uint32_t)mi * (16 * RSB) + koff;
                LDSM4(ah[0], ah[1], ah[2], ah[3], aa + OFF_AH);
                LDSM4(al[0], al[1], al[2], al[3], aa + OFF_AL);
#pragma unroll
                for (int ni = 0; ni < 4; ni++) {
                    MMA16816(acc[mi][ni], ah, bh[ni * 2], bh[ni * 2 + 1]);
                    MMA16816(acc[mi][ni], ah, bl[ni * 2], bl[ni * 2 + 1]);
                    MMA16816(acc[mi][ni], al, bh[ni * 2], bh[ni * 2 + 1]);
                }
            }
        }
    }
    __syncthreads();

    // ---- epilogue: per-row local top-2 over warp's 32 cols, then global top-2 push ----
    const int gid = lane >> 2, tig = lane & 3;
#pragma unroll
    for (int mi = 0; mi < 4; mi++) {
#pragma unroll
        for (int h = 0; h < 2; h++) {
            int grow = m0 + wm + mi * 16 + h * 8 + gid;
            unsigned long long b1 = ~0ULL, b2 = ~0ULL;
#pragma unroll
            for (int ni = 0; ni < 4; ni++) {
#pragma unroll
                for (int q = 0; q < 2; q++) {
                    int cl = wn + ni * 8 + tig * 2 + q;
                    float dist = s_cn2[cl] - 2.0f * acc[mi][ni][h * 2 + q];
                    unsigned long long p =
                        ((unsigned long long)float_key(dist) << 32) |
                        (unsigned int)(n0 + cl);
                    if (p < b1) { b2 = b1; b1 = p; }
                    else if (p < b2) { b2 = p; }
                }
            }
#pragma unroll
            for (int off = 1; off <= 2; off <<= 1) {
                unsigned long long o1 = __shfl_xor_sync(0xFFFFFFFFu, b1, off);
                unsigned long long o2 = __shfl_xor_sync(0xFFFFFFFFu, b2, off);
                unsigned long long n1 = b1 < o1 ? b1 : o1;
                unsigned long long hi = b1 < o1 ? o1 : b1;
                unsigned long long lo2 = b2 < o2 ? b2 : o2;
                b1 = n1;
                b2 = hi < lo2 ? hi : lo2;
            }
            if (tig == 0) {
                unsigned long long old = atomicMin(&g_rowmin[grow], b1);
                atomicMin(&g_rowmin2[grow], b1 < old ? old : b1);
                old = atomicMin(&g_rowmin[grow], b2);
                atomicMin(&g_rowmin2[grow], b2 < old ? old : b2);
            }
        }
    }
}

// ---------------- exact fp32 recheck for ambiguous rows ----------------
// One block per row; exits immediately unless top-2 gap < margin.
__global__ __launch_bounds__(256) void recheck_kernel() {
    const int row = blockIdx.x;
    const int tid = threadIdx.x;
    unsigned long long p1 = g_rowmin[row];
    unsigned long long p2 = g_rowmin2[row];
    float d1 = key_to_float((unsigned int)(p1 >> 32));
    float d2 = key_to_float((unsigned int)(p2 >> 32));
    if (d2 - d1 > 1e-4f) return;

    __shared__ float zrow[Dd];
    __shared__ unsigned long long red[256];
    zrow[tid] = g_zf[(size_t)row * Dd + tid];
    __syncthreads();

    unsigned long long best = ~0ULL;
    for (int k = tid; k < KCODES; k += 256) {
        const float* cp = g_Cb + (size_t)k * Dd;
        float dot = 0.f;
#pragma unroll 8
        for (int j = 0; j < Dd; j++) dot += zrow[j] * cp[j];
        float dist = g_cn2[k] - 2.0f * dot;
        unsigned long long p =
            ((unsigned long long)float_key(dist) << 32) | (unsigned int)k;
        best = p < best ? p : best;
    }
    red[tid] = best; __syncthreads();
    for (int o = 128; o; o >>= 1) {
        if (tid < o && red[tid + o] < red[tid]) red[tid] = red[tid + o];
        __syncthreads();
    }
    if (tid == 0) g_rowmin[row] = red[0];
}

// ---------------- gather chosen codes, loss partials, histogram ----------------
__global__ void gather_kernel() {
    int tid = threadIdx.x;
    float lsum = 0.f;
#pragma unroll
    for (int r = 0; r < 8; r++) {
        int n = blockIdx.x * 8 + r;
        unsigned int idx = (unsigned int)(g_rowmin[n] & 0xFFFFFFFFULL);
        float c = g_Cb[(size_t)idx * Dd + tid];
        float zv = g_zf[(size_t)n * Dd + tid];
        g_zq[(size_t)n * Dd + tid] = zv + (c - zv);
        float d = c - zv;
        lsum += d * d;
        if (tid == 0) atomicAdd(&g_counts[idx], 1);
    }
    __shared__ float red[256];
    red[tid] = lsum; __syncthreads();
    for (int o = 128; o; o >>= 1) { if (tid < o) red[tid] += red[tid + o]; __syncthreads(); }
    if (tid == 0) atomicAdd(&g_losssum, (double)red[0]);
}

// ---------------- scalars ----------------
__global__ void finalize_kernel(float* __restrict__ out_scalars) {
    __shared__ double red[256];
    int tid = threadIdx.x;

    double s = 0.0;
    for (int k = tid; k < KCODES; k += 256) s += (double)g_cn2[k];
    red[tid] = s; __syncthreads();
    for (int o = 128; o; o >>= 1) { if (tid < o) red[tid] += red[tid + o]; __syncthreads(); }
    double c2sum = red[0]; __syncthreads();

    red[tid] = (double)g_zsum[tid] * (double)g_csum[tid]; __syncthreads();
    for (int o = 128; o; o >>= 1) { if (tid < o) red[tid] += red[tid + o]; __syncthreads(); }
    double dot = red[0]; __syncthreads();

    double e = 0.0;
    for (int k = tid; k < KCODES; k += 256) {
        float p = (float)g_counts[k] / (float)NROWS;
        e += (double)(p * logf(p + 1e-10f));
    }
    red[tid] = e; __syncthreads();
    for (int o = 128; o; o >>= 1) { if (tid < o) red[tid] += red[tid + o]; __syncthreads(); }
    double ent = red[0];

    if (tid == 0) {
        double loss = 1.25 * g_losssum / ((double)NROWS * (double)Dd);
        double md = g_z2sum / (double)NROWS + c2sum / (double)KCODES
                  - 2.0 * dot / ((double)NROWS * (double)KCODES);
        out_scalars[0] = (float)loss;
        out_scalars[1] = expf((float)(-ent));
        out_scalars[2] = (float)md;
    }
}

// ---------------- launcher ----------------
extern "C" void kernel_launch(void* const* d_in, const int* in_sizes, int n_in,
                              void* d_out, int out_size) {
    const float* z    = (const float*)d_in[0];   // [2,256,8,32,32]
    const float* emb  = (const float*)d_in[1];   // [8192,256]
    const float* w1   = (const float*)d_in[2];   // [256,256]
    const float* w2   = (const float*)d_in[3];   // [256,256]
    float* out = (float*)d_out;

    static float *zf = nullptr, *Hb = nullptr, *Cb = nullptr;
    if (!zf) {
        cudaGetSymbolAddress((void**)&zf, g_zf);
        cudaGetSymbolAddress((void**)&Hb, g_Hb);
        cudaGetSymbolAddress((void**)&Cb, g_Cb);
    }

    init_kernel<<<64, 256>>>();
    transpose_in_kernel<<<dim3(HW / 32, Dd / 32, Bb * Tt), dim3(32, 8)>>>(z);
    split_z_kernel<<<NROWS * Dd / 256, 256>>>();
    colsum_z_kernel<<<NROWS / 64, 256>>>();

    // codebook: H = gelu(emb @ w1^T); C = H @ w2^T  (fp32-exact)
    gemm_nt_kernel<1><<<dim3(Dd / BN, KCODES / BM), 256>>>(emb, w1, Hb);
    gemm_nt_kernel<0><<<dim3(Dd / BN, KCODES / BM), 256>>>(Hb, w2, Cb);
    split_c_kernel<<<KCODES * Dd / 256, 256>>>();
    rownorm_kernel<<<KCODES / 8, 256>>>();
    colsum_c_kernel<<<KCODES / 64, 256>>>();

    // main distance GEMM + fused top-2 argmin on HMMA (mma.sync bf16x3)
    vq_dist_hmma_kernel<<<dim3(KCODES / 128, NROWS / 128), 256>>>();

    // exact fp32 re-argmin for rows whose top-2 gap is within error margin
    recheck_kernel<<<NROWS, 256>>>();

    gather_kernel<<<NROWS / 8, 256>>>();
    transpose_out_kernel<<<dim3(HW / 32, Dd / 32, Bb * Tt), dim3(32, 8)>>>(out);
    finalize_kernel<<<1, 256>>>(out + (size_t)Bb * Dd * Tt * HW);
}